// round 7
// baseline (speedup 1.0000x reference)
#include <cuda_runtime.h>

// PaillerMLP: out = W3 @ ((W2 @ ((W1 @ x + b1)^2) + b2)^2) + b3
// D_IN=4096, D_HID=8192, D_OUT=1000, all fp32. HBM-bound: ~415 MiB weights.
//
// R4: 78.6us, DRAM 69%. R5 (occupancy): 78.3us NEUTRAL — limit was not warps.
// R6: work-quantization fix. Warp-per-row gave 1.73 rows/warp-slot -> 86%
//     utilization ceiling. Split rows into K-segments (S=8), warp-per-segment,
//     partials to a per-(row,seg) array, tiny finalize kernel applies
//     bias + square. 13.8 items/warp -> ~93% utilization.

#define D_IN  4096
#define D_HID 8192
#define D_OUT 1000

// Scratch (__device__ globals — allocation rules forbid malloc).
__device__ float g_part1[8 * D_HID];   // layer-1 partials [seg][row]
__device__ float g_part2[8 * D_HID];   // layer-2 partials
__device__ float g_part3[4 * D_OUT];   // layer-3 partials
__device__ float g_h1[D_HID];
__device__ float g_h2[D_HID];

// Segmented warp-per-(row,segment) matvec partial.
// grid = (ceil(M/8)) * S blocks, seg-major: seg = blockIdx.x / nrg.
// Block stages its x-segment (K/S floats) in smem, shared by 8 warps.
// part[seg*M + row] = dot(W[row][seg*C : (seg+1)*C], x[seg*C : ...])
template <int K, int S>
__global__ __launch_bounds__(256, 4)
void matvec_seg_kernel(const float* __restrict__ W,
                       const float* __restrict__ x,
                       float* __restrict__ part,
                       int M)
{
    constexpr int C  = K / S;      // floats per segment
    constexpr int C4 = C / 4;      // float4 per segment
    constexpr int ITERS = C4 / 32; // float4 per lane in this segment
    constexpr int CHUNK = (ITERS < 8) ? ITERS : 8;

    __shared__ float4 sx4[C4];

    const int tid = threadIdx.x;
    const int nrg = gridDim.x / S;           // row groups (ceil(M/8))
    const int rg  = blockIdx.x % nrg;
    const int seg = blockIdx.x / nrg;

    // Stage this segment of x into shared.
    const float4* x4 = reinterpret_cast<const float4*>(x) + seg * C4;
    #pragma unroll
    for (int i = tid; i < C4; i += 256) sx4[i] = x4[i];
    __syncthreads();

    const int wid  = tid >> 5;
    const int lane = tid & 31;
    const int row  = rg * 8 + wid;
    if (row >= M) return;

    const float4* W4 = reinterpret_cast<const float4*>(W)
                     + (size_t)row * (K / 4) + seg * C4;

    float acc0 = 0.0f, acc1 = 0.0f;

    #pragma unroll
    for (int base = 0; base < ITERS; base += CHUNK) {
        float4 w[CHUNK];
        #pragma unroll
        for (int u = 0; u < CHUNK; u++)
            w[u] = __ldcs(&W4[(base + u) * 32 + lane]);   // stream, touched once
        #pragma unroll
        for (int u = 0; u < CHUNK; u++) {
            const float4 xv = sx4[(base + u) * 32 + lane];
            if (u & 1)
                acc1 += w[u].x * xv.x + w[u].y * xv.y + w[u].z * xv.z + w[u].w * xv.w;
            else
                acc0 += w[u].x * xv.x + w[u].y * xv.y + w[u].z * xv.z + w[u].w * xv.w;
        }
    }

    float acc = acc0 + acc1;
    #pragma unroll
    for (int off = 16; off; off >>= 1)
        acc += __shfl_xor_sync(0xffffffffu, acc, off);

    if (lane == 0)
        part[seg * M + row] = acc;
}

// h[i] = act( sum_s part[s*M + i] + b[i] ),  act = square or identity.
template <int S, bool SQUARE>
__global__ void finalize_kernel(const float* __restrict__ part,
                                const float* __restrict__ b,
                                float* __restrict__ h,
                                int M)
{
    const int i = blockIdx.x * blockDim.x + threadIdx.x;
    if (i >= M) return;
    float v = b[i];
    #pragma unroll
    for (int s = 0; s < S; s++)
        v += part[s * M + i];
    if (SQUARE) v = v * v;
    h[i] = v;
}

extern "C" void kernel_launch(void* const* d_in, const int* in_sizes, int n_in,
                              void* d_out, int out_size)
{
    const float* x  = (const float*)d_in[0];
    const float* W1 = (const float*)d_in[1];
    const float* b1 = (const float*)d_in[2];
    const float* W2 = (const float*)d_in[3];
    const float* b2 = (const float*)d_in[4];
    const float* W3 = (const float*)d_in[5];
    const float* b3 = (const float*)d_in[6];
    float* out = (float*)d_out;

    float *p1, *p2, *p3, *h1, *h2;
    cudaGetSymbolAddress((void**)&p1, g_part1);
    cudaGetSymbolAddress((void**)&p2, g_part2);
    cudaGetSymbolAddress((void**)&p3, g_part3);
    cudaGetSymbolAddress((void**)&h1, g_h1);
    cudaGetSymbolAddress((void**)&h2, g_h2);

    // Layer 1: [8192 x 4096], S=8 -> seg = 512 floats, 4 LDG.128/lane/item.
    matvec_seg_kernel<D_IN, 8><<<(D_HID / 8) * 8, 256>>>(W1, x, p1, D_HID);
    finalize_kernel<8, true><<<(D_HID + 255) / 256, 256>>>(p1, b1, h1, D_HID);

    // Layer 2: [8192 x 8192], S=8 -> seg = 1024 floats, 8 LDG.128/lane/item.
    matvec_seg_kernel<D_HID, 8><<<(D_HID / 8) * 8, 256>>>(W2, h1, p2, D_HID);
    finalize_kernel<8, true><<<(D_HID + 255) / 256, 256>>>(p2, b2, h2, D_HID);

    // Layer 3: [1000 x 8192], S=4 -> seg = 2048 floats, 16 LDG.128/lane/item.
    matvec_seg_kernel<D_HID, 4><<<((D_OUT + 7) / 8) * 4, 256>>>(W3, h2, p3, D_OUT);
    finalize_kernel<4, false><<<(D_OUT + 255) / 256, 256>>>(p3, b3, out, D_OUT);
}

// round 10
// speedup vs baseline: 1.0458x; 1.0458x over previous
#include <cuda_runtime.h>

// PaillerMLP: out = W3 @ ((W2 @ ((W1 @ x + b1)^2) + b2)^2) + b3
// D_IN=4096, D_HID=8192, D_OUT=1000, fp32. HBM-bound: ~415 MiB weights.
//
// R5 (3 big kernels):        78.3us, DRAM 71%, quantization-limited (1.73 rows/warp-slot).
// R6 (+segmentation, 6 krn): 84.0us — matvecs improved but 3 tiny finalize
//                            kernels cost ~4us each (launch floor).
// R7: ONE persistent kernel. Segmented matvec phases + software grid barriers.
//     Finalize of layers 1-2 fused into the consumer's x-staging (partials
//     stored [row][seg] so an element's 8 partials are 2 LDG.128).

#define D_IN  4096
#define D_HID 8192
#define D_OUT 1000
#define S1 8
#define S2 8
#define S3 32

// Scratch (__device__ globals — allocation APIs are forbidden).
__device__ float g_p1[D_HID * S1];     // layer-1 partials [row][seg]
__device__ float g_p2[D_HID * S2];     // layer-2 partials [row][seg]
__device__ float g_p3[D_OUT * S3];     // layer-3 partials [row][seg]
__device__ unsigned g_cnt;             // barrier counter (zero-init, self-resetting)

// ---- software grid barrier (all blocks co-resident by construction) ----
__device__ __forceinline__ void grid_barrier(unsigned target)
{
    __syncthreads();
    if (threadIdx.x == 0) {
        __threadfence();                       // publish this block's writes
        atomicAdd(&g_cnt, 1u);
        while (*(volatile unsigned*)&g_cnt < target)
            __nanosleep(64);
        __threadfence();
    }
    __syncthreads();
}

// ---- stage a segment of x into shared ----
// MODE 0: plain copy from x.
// MODE 1: fused finalize: x[i] = (b_prev[i] + sum_{s<SP} p_prev[i*SP+s])^2
template <int C, int SP, int MODE>
__device__ __forceinline__ void stage_segment(float* sxf, int seg,
                                              const float* __restrict__ xsrc,
                                              const float* __restrict__ p_prev,
                                              const float* __restrict__ b_prev)
{
    const int tid = threadIdx.x;
    if (MODE == 0) {
        const float4* xs = reinterpret_cast<const float4*>(xsrc) + seg * (C / 4);
        float4* s4 = reinterpret_cast<float4*>(sxf);
        #pragma unroll
        for (int i = tid; i < C / 4; i += 256)
            s4[i] = __ldcg(&xs[i]);
    } else {
        #pragma unroll 2
        for (int i = tid; i < C; i += 256) {
            const int gi = seg * C + i;
            const float4* pp = reinterpret_cast<const float4*>(p_prev + (size_t)gi * SP);
            float v = __ldcg(&b_prev[gi]);
            #pragma unroll
            for (int q = 0; q < SP / 4; q++) {
                float4 a = __ldcg(&pp[q]);
                v += a.x + a.y + a.z + a.w;
            }
            v = v * v;
            sxf[i] = v;
        }
    }
}

// ---- segmented matvec phase ----
// Items = (rowgroup, segment) pairs, seg-major so a block's contiguous chunk
// stays within one segment (stage once, reuse across items).
// part[row*S + seg] = dot(W[row][seg*C:(seg+1)*C], x_seg)
template <int K, int S, int SP, int MODE>
__device__ __forceinline__ void matvec_phase(const float* __restrict__ W,
                                             const float* __restrict__ xsrc,
                                             const float* __restrict__ p_prev,
                                             const float* __restrict__ b_prev,
                                             float* __restrict__ part,
                                             int M, float* sxf)
{
    constexpr int C     = K / S;          // floats per segment
    constexpr int C4    = C / 4;
    constexpr int ITERS = C4 / 32;        // float4 per lane per item
    constexpr int CHUNK = (ITERS < 8) ? ITERS : 8;

    const int nrg   = M / 8;              // row groups (M is a multiple of 8)
    const int total = nrg * S;
    const int g     = gridDim.x;
    const int ipb   = (total + g - 1) / g;
    const int start = blockIdx.x * ipb;
    const int end   = (start + ipb < total) ? (start + ipb) : total;

    const int tid  = threadIdx.x;
    const int wid  = tid >> 5;
    const int lane = tid & 31;
    const float4* sx4 = reinterpret_cast<const float4*>(sxf);

    int cur_seg = -1;
    for (int item = start; item < end; item++) {
        const int seg = item / nrg;
        const int rg  = item - seg * nrg;

        if (seg != cur_seg) {             // uniform per block
            __syncthreads();
            stage_segment<C, SP, MODE>(sxf, seg, xsrc, p_prev, b_prev);
            __syncthreads();
            cur_seg = seg;
        }

        const int row = rg * 8 + wid;
        const float4* W4 = reinterpret_cast<const float4*>(W)
                         + (size_t)row * (K / 4) + seg * C4;

        float acc0 = 0.0f, acc1 = 0.0f;
        #pragma unroll
        for (int base = 0; base < ITERS; base += CHUNK) {
            float4 w[CHUNK];
            #pragma unroll
            for (int u = 0; u < CHUNK; u++)
                w[u] = __ldcs(&W4[(base + u) * 32 + lane]);   // stream: touched once
            #pragma unroll
            for (int u = 0; u < CHUNK; u++) {
                const float4 xv = sx4[(base + u) * 32 + lane];
                if (u & 1)
                    acc1 += w[u].x * xv.x + w[u].y * xv.y + w[u].z * xv.z + w[u].w * xv.w;
                else
                    acc0 += w[u].x * xv.x + w[u].y * xv.y + w[u].z * xv.z + w[u].w * xv.w;
            }
        }

        float acc = acc0 + acc1;
        #pragma unroll
        for (int off = 16; off; off >>= 1)
            acc += __shfl_xor_sync(0xffffffffu, acc, off);

        if (lane == 0)
            part[(size_t)row * S + seg] = acc;
    }
}

// ---- final output: out[i] = b3[i] + sum_s p3[i*S3+s] ----
__device__ __forceinline__ void fin3_phase(const float* __restrict__ p,
                                           const float* __restrict__ b,
                                           float* __restrict__ out)
{
    const int stride = gridDim.x * 256;
    for (int i = blockIdx.x * 256 + threadIdx.x; i < D_OUT; i += stride) {
        const float4* pp = reinterpret_cast<const float4*>(p + (size_t)i * S3);
        float v = b[i];
        #pragma unroll
        for (int q = 0; q < S3 / 4; q++) {
            float4 a = __ldcg(&pp[q]);
            v += a.x + a.y + a.z + a.w;
        }
        out[i] = v;
    }
}

__global__ __launch_bounds__(256, 4)
void mlp_persistent(const float* __restrict__ x,
                    const float* __restrict__ W1, const float* __restrict__ b1,
                    const float* __restrict__ W2, const float* __restrict__ b2,
                    const float* __restrict__ W3, const float* __restrict__ b3,
                    float* __restrict__ out)
{
    __shared__ float sxf[D_HID / S2];     // 1024 floats = 4KB (max segment)
    const unsigned g = gridDim.x;

    // Phase 1: p1 = segmented W1 @ x            [8192 x 4096], S=8, C=512
    matvec_phase<D_IN, S1, 1, 0>(W1, x, nullptr, nullptr, g_p1, D_HID, sxf);
    grid_barrier(1u * g);

    // Phase 2: p2 = segmented W2 @ h1, h1 fused in staging. S=8, C=1024
    matvec_phase<D_HID, S2, S1, 1>(W2, nullptr, g_p1, b1, g_p2, D_HID, sxf);
    grid_barrier(2u * g);

    // Phase 3: p3 = segmented W3 @ h2, h2 fused in staging. S=32, C=256
    matvec_phase<D_HID, S3, S2, 1>(W3, nullptr, g_p2, b2, g_p3, D_OUT, sxf);
    grid_barrier(3u * g);

    // Phase 4: out = sum(p3) + b3
    fin3_phase(g_p3, b3, out);

    // Final arrival: last block resets the counter -> identical state next replay.
    __syncthreads();
    if (threadIdx.x == 0) {
        __threadfence();
        unsigned old = atomicAdd(&g_cnt, 1u);
        if (old == 4u * g - 1u)
            g_cnt = 0;
    }
}

extern "C" void kernel_launch(void* const* d_in, const int* in_sizes, int n_in,
                              void* d_out, int out_size)
{
    const float* x  = (const float*)d_in[0];
    const float* W1 = (const float*)d_in[1];
    const float* b1 = (const float*)d_in[2];
    const float* W2 = (const float*)d_in[3];
    const float* b2 = (const float*)d_in[4];
    const float* W3 = (const float*)d_in[5];
    const float* b3 = (const float*)d_in[6];
    float* out = (float*)d_out;

    // Host-side queries: not stream ops, legal under graph capture. The grid
    // size is frozen into the captured graph; all blocks are co-resident by
    // construction, so the in-kernel spin barriers cannot deadlock.
    int dev = 0;
    cudaGetDevice(&dev);
    int sms = 148;
    cudaDeviceGetAttribute(&sms, cudaDevAttrMultiProcessorCount, dev);
    int nb = 0;
    cudaOccupancyMaxActiveBlocksPerMultiprocessor(&nb, mlp_persistent, 256, 0);
    if (nb < 1) nb = 1;
    int grid = sms * nb;

    mlp_persistent<<<grid, 256>>>(x, W1, b1, W2, b2, W3, b3, out);
}

// round 11
// speedup vs baseline: 1.0732x; 1.0262x over previous
#include <cuda_runtime.h>

// PaillerMLP: out = W3 @ ((W2 @ ((W1 @ x + b1)^2) + b2)^2) + b3
// D_IN=4096, D_HID=8192, D_OUT=1000, fp32. HBM-bound: ~415 MiB weights.
//
// R5 (3 kernels, warp/row):  78.3us, DRAM 71% — quantization tails.
// R7 (persistent + 3 global barriers): 80.4us, DRAM 66% — barrier stalls.
// R10: persistent kernel, NO mid barriers. Per-segment producer/consumer
//      counters (release = fence+red on block flush, acquire = spin):
//      phase tails overlap the next phase's head. Item orderings chosen so
//      every dependency's producers form a contiguous item range.

#define D_IN  4096
#define D_HID 8192
#define D_OUT 1000

#define S1 8                    // layer-1 K-segments, C1 = 512
#define S2 8                    // layer-2 K-segments, C2 = 1024
#define S3 32                   // layer-3 K-segments, C3 = 256
#define NRG1 (D_HID / 8)        // 1024 rowgroups (8 rows each)
#define NRG2 (D_HID / 8)        // 1024
#define NRG3 (D_OUT / 8)        // 125
#define ITEMS1 (NRG1 * S1)      // 8192  item = rg*8 + t   (rg-major)
#define ITEMS2 (NRG2 * S2)      // 8192  item = chunk*256 + s*32 + rg_in
#define ITEMS3 (NRG3 * S3)      // 4000  item = u*125 + rgi (seg-major)

// Scratch (__device__ globals — allocation APIs forbidden).
__device__ __align__(16) float g_p1[D_HID * S1];   // [row][seg]
__device__ __align__(16) float g_p2[D_HID * S2];   // [row][seg]
__device__ __align__(16) float g_p3[D_OUT * S3];   // [row][seg]
__device__ unsigned g_cnt1[S1];     // h1 seg s ready when == 1024
__device__ unsigned g_cnt2[S3];     // h2 seg u ready when == 256  (32 chunks)
__device__ unsigned g_bar;          // final barrier / reset

__device__ __forceinline__ void split(int total, int g, int b, int& s, int& e)
{
    int base = total / g, rem = total % g;
    s = b * base + (b < rem ? b : rem);
    e = s + base + (b < rem ? 1 : 0);
}

// Producer release: all block threads' global stores for the flushed items
// happen-before (via bar.sync) tid0's fence+red.
__device__ __forceinline__ void flush(unsigned* cnt, int n)
{
    __syncthreads();
    if (threadIdx.x == 0) {
        __threadfence();
        atomicAdd(cnt, (unsigned)n);
    }
}

// Consumer acquire: spin until target, fence, then block reads.
__device__ __forceinline__ void acquire(unsigned* cnt, unsigned target)
{
    __syncthreads();
    if (threadIdx.x == 0) {
        while (*(volatile unsigned*)cnt < target)
            __nanosleep(32);
        __threadfence();
    }
    __syncthreads();
}

// Warp dot-product over one K-segment: NV float4 per lane, front-batched.
template <int NV>
__device__ __forceinline__ float seg_dot(const float4* __restrict__ Wp,
                                         const float4* __restrict__ xv4,
                                         int lane)
{
    float4 w[NV];
    #pragma unroll
    for (int u = 0; u < NV; u++)
        w[u] = __ldcs(&Wp[u * 32 + lane]);          // streamed, touched once
    float a0 = 0.f, a1 = 0.f;
    #pragma unroll
    for (int u = 0; u < NV; u++) {
        const float4 xv = xv4[u * 32 + lane];
        if (u & 1) a1 += w[u].x*xv.x + w[u].y*xv.y + w[u].z*xv.z + w[u].w*xv.w;
        else       a0 += w[u].x*xv.x + w[u].y*xv.y + w[u].z*xv.z + w[u].w*xv.w;
    }
    float acc = a0 + a1;
    #pragma unroll
    for (int off = 16; off; off >>= 1)
        acc += __shfl_xor_sync(0xffffffffu, acc, off);
    return acc;
}

// Same but x comes straight from global (L1-resident 16KB vector).
template <int NV>
__device__ __forceinline__ float seg_dot_g(const float4* __restrict__ Wp,
                                           const float4* __restrict__ xg4,
                                           int lane)
{
    float4 w[NV];
    #pragma unroll
    for (int u = 0; u < NV; u++)
        w[u] = __ldcs(&Wp[u * 32 + lane]);
    float a0 = 0.f, a1 = 0.f;
    #pragma unroll
    for (int u = 0; u < NV; u++) {
        const float4 xv = __ldg(&xg4[u * 32 + lane]);
        if (u & 1) a1 += w[u].x*xv.x + w[u].y*xv.y + w[u].z*xv.z + w[u].w*xv.w;
        else       a0 += w[u].x*xv.x + w[u].y*xv.y + w[u].z*xv.z + w[u].w*xv.w;
    }
    float acc = a0 + a1;
    #pragma unroll
    for (int off = 16; off; off >>= 1)
        acc += __shfl_xor_sync(0xffffffffu, acc, off);
    return acc;
}

// Fused finalize staging: sxf[i] = (b_prev[g0+i] + sum_q p_prev[(g0+i)*SP+q])^2
template <int C, int SP>
__device__ __forceinline__ void stage_fin(float* sxf, int g0,
                                          const float* __restrict__ p_prev,
                                          const float* __restrict__ b_prev)
{
    for (int i = threadIdx.x; i < C; i += 256) {
        const int gi = g0 + i;
        const float4* pp = reinterpret_cast<const float4*>(p_prev + (size_t)gi * SP);
        float v = __ldg(&b_prev[gi]);
        #pragma unroll
        for (int q = 0; q < SP / 4; q++) {
            float4 a = __ldcg(&pp[q]);
            v += a.x + a.y + a.z + a.w;
        }
        sxf[i] = v * v;
    }
}

__global__ __launch_bounds__(256, 4)
void mlp_persistent(const float* __restrict__ x,
                    const float* __restrict__ W1, const float* __restrict__ b1,
                    const float* __restrict__ W2, const float* __restrict__ b2,
                    const float* __restrict__ W3, const float* __restrict__ b3,
                    float* __restrict__ out)
{
    __shared__ float sxf[D_HID / S2];       // 1024 floats = 4KB (max segment)
    const int g    = gridDim.x;
    const int b    = blockIdx.x;
    const int tid  = threadIdx.x;
    const int wid  = tid >> 5;
    const int lane = tid & 31;

    // ---------- Phase 1: p1[row][t] = dot(W1[row][t*512:...], x_seg) ----------
    // rg-major items: consecutive items share a rowgroup -> each warp walks its
    // W1 row contiguously. h1 seg s <- items [1024s, 1024(s+1)) contiguous.
    {
        int s, e; split(ITEMS1, g, b, s, e);
        int it = s;
        while (it < e) {
            const int seg   = it >> 10;                     // h1 segment
            const int stop  = min(e, (seg + 1) << 10);
            const int first = it;
            for (; it < stop; it++) {
                const int rg = it >> 3, t = it & 7;
                const int row = rg * 8 + wid;
                const float4* Wp = reinterpret_cast<const float4*>(W1)
                                 + (size_t)row * (D_IN / 4) + t * 128;
                const float4* xg = reinterpret_cast<const float4*>(x) + t * 128;
                float acc = seg_dot_g<4>(Wp, xg, lane);
                if (lane == 0) g_p1[row * S1 + t] = acc;
            }
            flush(&g_cnt1[seg], stop - first);
        }
    }

    // ---------- Phase 2: p2[row][s] = dot(W2[row][s*1024:...], h1_seg) ----------
    // item = chunk*256 + s*32 + rg_in ; rg = chunk*32 + rg_in.
    // h2 chunk u <- items [256u, 256(u+1)) contiguous -> cnt2[u] target 256.
    {
        int s0, e0; split(ITEMS2, g, b, s0, e0);
        int it = s0, cur_s = -1;
        while (it < e0) {
            const int chunk = it >> 8;
            const int chunk_stop = min(e0, (chunk + 1) << 8);
            const int chunk_first = it;
            while (it < chunk_stop) {
                const int sK = (it >> 5) & 7;
                const int stop = min(chunk_stop, ((it >> 5) + 1) << 5);
                if (sK != cur_s) {
                    acquire(&g_cnt1[sK], 1024u);
                    stage_fin<D_HID / S2, S1>(sxf, sK * (D_HID / S2), g_p1, b1);
                    __syncthreads();
                    cur_s = sK;
                }
                const float4* sx4 = reinterpret_cast<const float4*>(sxf);
                for (; it < stop; it++) {
                    const int rg  = chunk * 32 + (it & 31);
                    const int row = rg * 8 + wid;
                    const float4* Wp = reinterpret_cast<const float4*>(W2)
                                     + (size_t)row * (D_HID / 4) + sK * 256;
                    float acc = seg_dot<8>(Wp, sx4, lane);
                    if (lane == 0) g_p2[row * S2 + sK] = acc;
                }
            }
            flush(&g_cnt2[chunk], chunk_stop - chunk_first);
        }
    }

    // ---------- Phase 3: p3[row][u] = dot(W3[row][u*256:...], h2_seg u) ----------
    // seg-major: item = u*125 + rgi. Needs only h2 chunk u (cnt2[u] == 256).
    {
        int s0, e0; split(ITEMS3, g, b, s0, e0);
        int cur_u = -1;
        for (int it = s0; it < e0; it++) {
            const int u   = it / NRG3;
            const int rgi = it - u * NRG3;
            if (u != cur_u) {
                acquire(&g_cnt2[u], 256u);
                stage_fin<D_HID / S3, S2>(sxf, u * (D_HID / S3), g_p2, b2);
                __syncthreads();
                cur_u = u;
            }
            const float4* sx4 = reinterpret_cast<const float4*>(sxf);
            const int row = rgi * 8 + wid;
            const float4* Wp = reinterpret_cast<const float4*>(W3)
                             + (size_t)row * (D_HID / 4) + u * 64;
            float acc = seg_dot<2>(Wp, sx4, lane);
            if (lane == 0) g_p3[row * S3 + u] = acc;
        }
    }

    // ---------- Barrier, then fin3: out[i] = b3[i] + sum_u p3[i][u] ----------
    __syncthreads();
    if (tid == 0) {
        __threadfence();
        atomicAdd(&g_bar, 1u);
        while (*(volatile unsigned*)&g_bar < (unsigned)g)
            __nanosleep(32);
        __threadfence();
    }
    __syncthreads();

    for (int i = b * 256 + tid; i < D_OUT; i += g * 256) {
        const float4* pp = reinterpret_cast<const float4*>(g_p3 + (size_t)i * S3);
        float v = __ldg(&b3[i]);
        #pragma unroll
        for (int q = 0; q < S3 / 4; q++) {
            float4 a = __ldcg(&pp[q]);
            v += a.x + a.y + a.z + a.w;
        }
        out[i] = v;
    }

    // ---------- Reset counters for the next graph replay ----------
    __syncthreads();
    if (tid == 0) {
        __threadfence();
        unsigned old = atomicAdd(&g_bar, 1u);
        if (old == 2u * (unsigned)g - 1u) {        // last block out resets all
            #pragma unroll
            for (int i = 0; i < S1; i++) g_cnt1[i] = 0;
            #pragma unroll
            for (int i = 0; i < S3; i++) g_cnt2[i] = 0;
            g_bar = 0;
        }
    }
}

extern "C" void kernel_launch(void* const* d_in, const int* in_sizes, int n_in,
                              void* d_out, int out_size)
{
    const float* x  = (const float*)d_in[0];
    const float* W1 = (const float*)d_in[1];
    const float* b1 = (const float*)d_in[2];
    const float* W2 = (const float*)d_in[3];
    const float* b2 = (const float*)d_in[4];
    const float* W3 = (const float*)d_in[5];
    const float* b3 = (const float*)d_in[6];
    float* out = (float*)d_out;

    // Host-side queries are not stream ops — legal under graph capture; grid
    // size freezes into the graph. grid = resident capacity, so the in-kernel
    // spins cannot deadlock.
    int dev = 0;
    cudaGetDevice(&dev);
    int sms = 148;
    cudaDeviceGetAttribute(&sms, cudaDevAttrMultiProcessorCount, dev);
    int nb = 0;
    cudaOccupancyMaxActiveBlocksPerMultiprocessor(&nb, mlp_persistent, 256, 0);
    if (nb < 1) nb = 1;
    int grid = sms * nb;

    mlp_persistent<<<grid, 256>>>(x, W1, b1, W2, b2, W3, b3, out);
}